// round 16
// baseline (speedup 1.0000x reference)
#include <cuda_runtime.h>
#include <cuda_bf16.h>
#include <math.h>
#include <stdint.h>

#define ACT_NONE 0
#define ACT_RELU 1
#define ACT_TANH 2
#define ACT_SIG  3

// ---- scratch buffer partition (floats) ----
constexpr size_t N_X1   = 8ull*16*256*256;
constexpr size_t N_P1   = 8ull*16*128*128;
constexpr size_t N_X2   = 8ull*32*128*128;
constexpr size_t N_P2   = 8ull*32*64*64;
constexpr size_t N_X3   = 8ull*32*64*64;
constexpr size_t N_P3   = 8ull*32*32*32;
constexpr size_t N_X4   = 8ull*32*32*32;
constexpr size_t N_P4   = 8ull*32*16*16;
constexpr size_t N_X5   = 8ull*64*16*16;
constexpr size_t N_X6   = 8ull*32*32*32;
constexpr size_t N_X7   = 8ull*32*64*64;
constexpr size_t N_X8   = 8ull*32*128*128;
constexpr size_t N_FM   = 8ull*64*256*256;
constexpr size_t N_XIN  = 8ull*16*256*256;
constexpr size_t N_RMAX = 8ull*16*256*256;
constexpr size_t N_WP   = 262144;

constexpr size_t O_X1   = 0;
constexpr size_t O_P1   = O_X1   + N_X1;
constexpr size_t O_X2   = O_P1   + N_P1;
constexpr size_t O_P2   = O_X2   + N_X2;
constexpr size_t O_X3   = O_P2   + N_P2;
constexpr size_t O_P3   = O_X3   + N_X3;
constexpr size_t O_X4   = O_P3   + N_P3;
constexpr size_t O_P4   = O_X4   + N_X4;
constexpr size_t O_X5   = O_P4   + N_P4;
constexpr size_t O_X6   = O_X5   + N_X5;
constexpr size_t O_X7   = O_X6   + N_X6;
constexpr size_t O_X8   = O_X7   + N_X7;
constexpr size_t O_FM   = O_X8   + N_X8;
constexpr size_t O_XIN  = O_FM   + N_FM;
constexpr size_t O_RMAX = O_XIN  + N_XIN;
constexpr size_t O_WP   = O_RMAX + N_RMAX;
constexpr size_t N_TOTAL = O_WP + N_WP;

__device__ float g_buf[N_TOTAL];

// prepped-weight offsets (u16 units; non-overlapping, verified)
constexpr int WOFF1 = 0;
constexpr int WOFF2 = 8192;
constexpr int WOFF3 = 16384;
constexpr int WOFF7 = 32768;
constexpr int WOFF8 = 53248;
constexpr int WOFF9 = 73728;
constexpr int WOFFI = 104448;
constexpr int WPLANE = 131072;

// ---- bf16 helpers ----
__device__ __forceinline__ void bf16_split(float v, uint16_t& hi, uint16_t& lo) {
    __nv_bfloat16 h = __float2bfloat16_rn(v);
    hi = __bfloat16_as_ushort(h);
    lo = __bfloat16_as_ushort(__float2bfloat16_rn(v - __bfloat162float(h)));
}
__device__ __forceinline__ int idx16(int c) {
    return (c < 8) ? (((c >> 1) << 2) + (c & 1))
                   : ((((c - 8) >> 1) << 2) + 2 + ((c - 8) & 1));
}
__device__ __forceinline__ void mma_bf16(float* c, const uint32_t* a,
                                         uint32_t b0, uint32_t b1) {
    asm volatile(
        "mma.sync.aligned.m16n8k16.row.col.f32.bf16.bf16.f32 "
        "{%0,%1,%2,%3}, {%4,%5,%6,%7}, {%8,%9}, {%0,%1,%2,%3};"
        : "+f"(c[0]), "+f"(c[1]), "+f"(c[2]), "+f"(c[3])
        : "r"(a[0]), "r"(a[1]), "r"(a[2]), "r"(a[3]), "r"(b0), "r"(b1));
}
// bilinear 2x upsample sample, half-pixel centers, edge clamp.
__device__ __forceinline__ float ups_sample(const float* __restrict__ p,
                                            int y, int x, int Hi, int Wi) {
    int xi = x >> 1, yi = y >> 1;
    int xa, xb; float wxa;
    if (x & 1) { xa = xi; xb = min(xi + 1, Wi - 1); wxa = 0.75f; }
    else       { xa = max(xi - 1, 0); xb = xi;      wxa = 0.25f; }
    int ya, yb; float wya;
    if (y & 1) { ya = yi; yb = min(yi + 1, Hi - 1); wya = 0.75f; }
    else       { ya = max(yi - 1, 0); yb = yi;      wya = 0.25f; }
    float r0 = wxa * p[ya * Wi + xa] + (1.f - wxa) * p[ya * Wi + xb];
    float r1 = wxa * p[yb * Wi + xa] + (1.f - wxa) * p[yb * Wi + xb];
    return wya * r0 + (1.f - wya) * r1;
}

// ===================================================================
// Fused weight prep (verified).
// ===================================================================
__global__ void prep_all_kernel(
    const float* __restrict__ w1, const float* __restrict__ w2,
    const float* __restrict__ w3, const float* __restrict__ w7,
    const float* __restrict__ w8, const float* __restrict__ w9,
    const float* __restrict__ wi,
    uint16_t* __restrict__ wph, uint16_t* __restrict__ wpl)
{
    const int cum[8] = {0, 6400, 11008, 20224, 38656, 57088, 84736, 87040};
    int idx = blockIdx.x * 256 + threadIdx.x;
    if (idx >= 87040) return;
    int l = 0;
    while (idx >= cum[l + 1]) l++;
    int local = idx - cum[l];

    const float* wsrc; int Cin, Cout, KK, woff;
    switch (l) {
        case 0: wsrc = w1; Cin = 15; Cout = 16; KK = 25; woff = WOFF1; break;
        case 1: wsrc = w2; Cin = 16; Cout = 32; KK = 9;  woff = WOFF2; break;
        case 2: wsrc = w3; Cin = 32; Cout = 32; KK = 9;  woff = WOFF3; break;
        case 3: wsrc = w7; Cin = 64; Cout = 32; KK = 9;  woff = WOFF7; break;
        case 4: wsrc = w8; Cin = 64; Cout = 32; KK = 9;  woff = WOFF8; break;
        case 5: wsrc = w9; Cin = 48; Cout = 64; KK = 9;  woff = WOFF9; break;
        default: wsrc = wi; Cin = 15; Cout = 16; KK = 9; woff = WOFFI; break;
    }
    int ch = local & 15;
    int r  = local >> 4;
    int n  = r % Cout;
    int r2 = r / Cout;
    int t  = r2 % KK;
    int g  = r2 / KK;
    int cin = g * 16 + ch;
    float w = (cin < Cin) ? wsrc[((size_t)n * Cin + cin) * KK + t] : 0.f;
    uint16_t h, lo;
    bf16_split(w, h, lo);
    int p = woff + ((g * KK + t) * Cout + n) * 16 + idx16(ch);
    wph[p] = h;
    wpl[p] = lo;
}

// ===================================================================
// Tensor conv (R15 compute; staging batched in chunks of 8 for MLP).
// ===================================================================
template<int K, int N, int ACT, int UPSA>
__global__ void __launch_bounds__(128) tconv_kernel(
    const float* __restrict__ inA, int CA,
    const float* __restrict__ inB, int CB,
    const uint16_t* __restrict__ wph, const uint16_t* __restrict__ wpl,
    const float* __restrict__ bias,
    float* __restrict__ out, int H, int W, int co0, int Ctot)
{
    constexpr int KK   = K * K;
    constexpr int PAD  = K / 2;
    constexpr int SH   = 8 + K - 1;
    constexpr int SWI  = 16 + K - 1;
    constexpr int NPIX = SH * SWI;
    constexpr int RP   = 16;
    constexpr int NT   = N / 8;
    constexpr int TOT  = 16 * NPIX;
    constexpr int SITER = (TOT + 127) / 128;

    __shared__ __align__(16) uint16_t s_hi[NPIX * RP];
    __shared__ __align__(16) uint16_t s_lo[NPIX * RP];
    __shared__ __align__(16) uint16_t s_bh[KK * N * RP];
    __shared__ __align__(16) uint16_t s_bl[KK * N * RP];

    const int tid  = threadIdx.x;
    const int wid  = tid >> 5;
    const int lane = tid & 31;
    const int ql   = lane & 3;
    const int qr   = lane >> 2;
    const int x0 = blockIdx.x * 16, y0 = blockIdx.y * 8, b = blockIdx.z;
    const int Cin = CA + CB;
    const size_t HW  = (size_t)H * W;
    const size_t HWA = UPSA ? (HW >> 2) : HW;
    const int Hi = H >> 1, Wi = W >> 1;

    float acc[2][NT][4];
#pragma unroll
    for (int mt = 0; mt < 2; mt++)
#pragma unroll
        for (int nt = 0; nt < NT; nt++)
#pragma unroll
            for (int i = 0; i < 4; i++) acc[mt][nt][i] = 0.f;

    const int nG = (Cin + 15) >> 4;
    for (int gi = 0; gi < nG; gi++) {
        const int g0 = gi * 16;
        __syncthreads();
        // ---- stage halo: batched loads (MLP 8), then split+store ----
#pragma unroll
        for (int s0 = 0; s0 < SITER; s0 += 8) {
            float v[8];
            int pdst[8];
#pragma unroll
            for (int j = 0; j < 8; j++) {
                int s = s0 + j;
                int idx = tid + s * 128;
                float val = 0.f;
                int p = 0;
                if (s < SITER && idx < TOT) {
                    int ch  = idx / NPIX;
                    int pix = idx - ch * NPIX;
                    int iy = pix / SWI, ix = pix - iy * SWI;
                    int cin = g0 + ch;
                    if (cin < Cin) {
                        int gy = y0 + iy - PAD, gx = x0 + ix - PAD;
                        if ((unsigned)gy < (unsigned)H && (unsigned)gx < (unsigned)W) {
                            if (cin < CA) {
                                const float* src = inA + ((size_t)b * CA + cin) * HWA;
                                val = UPSA ? ups_sample(src, gy, gx, Hi, Wi)
                                           : src[(size_t)gy * W + gx];
                            } else {
                                const float* src = inB + ((size_t)b * CB + (cin - CA)) * HW;
                                val = src[(size_t)gy * W + gx];
                            }
                        }
                    }
                    p = pix * RP + idx16(ch);
                } else {
                    p = -1;
                }
                v[j] = val;
                pdst[j] = p;
            }
#pragma unroll
            for (int j = 0; j < 8; j++) {
                if (pdst[j] >= 0) {
                    uint16_t h, l;
                    bf16_split(v[j], h, l);
                    s_hi[pdst[j]] = h;
                    s_lo[pdst[j]] = l;
                }
            }
        }
        // ---- copy B records gmem -> smem, uint4 (contiguous) ----
        {
            const uint4* srcH = reinterpret_cast<const uint4*>(wph);
            const uint4* srcL = reinterpret_cast<const uint4*>(wpl);
            uint4* dstH = reinterpret_cast<uint4*>(s_bh);
            uint4* dstL = reinterpret_cast<uint4*>(s_bl);
            for (int u = tid; u < KK * N * 2; u += 128) {
                int q = u & 1;
                int r = u >> 1;
                int n = r % N;
                int t = r / N;
                int su = ((gi * KK + t) * Ctot + co0 + n) * 2 + q;
                dstH[u] = srcH[su];
                dstL[u] = srcL[su];
            }
        }
        __syncthreads();

        // ---- compute: KK taps ----
#pragma unroll
        for (int ky = 0; ky < K; ky++)
#pragma unroll
        for (int kx = 0; kx < K; kx++) {
            const int t = ky * K + kx;
            uint32_t aH[2][4], aL[2][4];
#pragma unroll
            for (int mt = 0; mt < 2; mt++) {
                int pixA = (2 * wid + mt + ky) * SWI + (qr + kx);
                uint2 h0 = *reinterpret_cast<const uint2*>(
                    &s_hi[pixA * RP + 4 * ql]);
                uint2 h1 = *reinterpret_cast<const uint2*>(
                    &s_hi[(pixA + 8) * RP + 4 * ql]);
                uint2 l0 = *reinterpret_cast<const uint2*>(
                    &s_lo[pixA * RP + 4 * ql]);
                uint2 l1 = *reinterpret_cast<const uint2*>(
                    &s_lo[(pixA + 8) * RP + 4 * ql]);
                aH[mt][0] = h0.x; aH[mt][1] = h1.x;
                aH[mt][2] = h0.y; aH[mt][3] = h1.y;
                aL[mt][0] = l0.x; aL[mt][1] = l1.x;
                aL[mt][2] = l0.y; aL[mt][3] = l1.y;
            }
#pragma unroll
            for (int nt = 0; nt < NT; nt++) {
                uint2 bh = *reinterpret_cast<const uint2*>(
                    &s_bh[(t * N + nt * 8 + qr) * RP + 4 * ql]);
                uint2 bl = *reinterpret_cast<const uint2*>(
                    &s_bl[(t * N + nt * 8 + qr) * RP + 4 * ql]);
#pragma unroll
                for (int mt = 0; mt < 2; mt++) {
                    mma_bf16(acc[mt][nt], aH[mt], bh.x, bh.y);
                    mma_bf16(acc[mt][nt], aH[mt], bl.x, bl.y);
                    mma_bf16(acc[mt][nt], aL[mt], bh.x, bh.y);
                }
            }
        }
    }

    // ---- epilogue ----
#pragma unroll
    for (int mt = 0; mt < 2; mt++) {
        int gy = y0 + 2 * wid + mt;
#pragma unroll
        for (int nt = 0; nt < NT; nt++) {
#pragma unroll
            for (int i = 0; i < 4; i++) {
                int co = co0 + nt * 8 + 2 * ql + (i & 1);
                int gx = x0 + qr + ((i >> 1) ? 8 : 0);
                float s = acc[mt][nt][i] + bias[co];
                if (ACT == ACT_RELU)      s = fmaxf(s, 0.f);
                else if (ACT == ACT_TANH) s = tanhf(s);
                else if (ACT == ACT_SIG)  s = 1.f / (1.f + expf(-s));
                out[((size_t)b * Ctot + co) * HW + (size_t)gy * W + gx] = s;
            }
        }
    }
}

// ===================================================================
// Scalar conv (R3 proven), optional fused upsample on inA.
// ===================================================================
template<int K, int COC, int ACT, int RPT, int UPSA>
__global__ void __launch_bounds__(128) conv_kernel(
    const float* __restrict__ inA, int CA,
    const float* __restrict__ inB, int CB,
    const float* __restrict__ wgt, const float* __restrict__ bias,
    float* __restrict__ out, int H, int W, int nChunk, int Ctot)
{
    constexpr int KK = K * K, PAD = K / 2, TH = 8 * RPT;
    constexpr int SW = (K == 3) ? 18 : 22;
    constexpr int SH = TH + K - 1;
    __shared__ float s_in[SH * SW];
    __shared__ __align__(16) float s_w[KK * COC];

    const int tx = threadIdx.x & 15, ty = threadIdx.x >> 4;
    const int x0 = blockIdx.x * 16, y0 = blockIdx.y * TH;
    const int z = blockIdx.z;
    const int b = z / nChunk, chunk = z - b * nChunk, co0 = chunk * COC;
    const int Cin = CA + CB;
    const size_t HW = (size_t)H * W;
    const size_t HWA = UPSA ? (HW >> 2) : HW;
    const int Hi = H >> 1, Wi = W >> 1;

    float acc[COC * RPT];
#pragma unroll
    for (int i = 0; i < COC * RPT; i++) acc[i] = 0.f;

    for (int cin = 0; cin < Cin; cin++) {
        __syncthreads();
        for (int i = threadIdx.x; i < SH * SW; i += 128) {
            int iy = i / SW, ix = i - iy * SW;
            int gy = y0 + iy - PAD, gx = x0 + ix - PAD;
            float v = 0.f;
            if ((unsigned)gy < (unsigned)H && (unsigned)gx < (unsigned)W) {
                if (cin < CA) {
                    const float* src = inA + ((size_t)b * CA + cin) * HWA;
                    v = UPSA ? ups_sample(src, gy, gx, Hi, Wi)
                             : src[(size_t)gy * W + gx];
                } else {
                    const float* src = inB + ((size_t)b * CB + (cin - CA)) * HW;
                    v = src[(size_t)gy * W + gx];
                }
            }
            s_in[i] = v;
        }
        for (int i = threadIdx.x; i < KK * COC; i += 128) {
            int k = i / COC, co = i - k * COC;
            s_w[i] = wgt[((size_t)(co0 + co) * Cin + cin) * KK + k];
        }
        __syncthreads();

#pragma unroll
        for (int k = 0; k < KK; k++) {
            const int ky = k / K, kx = k - ky * K;
            float v[RPT];
#pragma unroll
            for (int r = 0; r < RPT; r++)
                v[r] = s_in[(ty + 8 * r + ky) * SW + tx + kx];
            if (COC % 4 == 0) {
#pragma unroll
                for (int c4 = 0; c4 < COC / 4; c4++) {
                    float4 w = *reinterpret_cast<const float4*>(&s_w[k * COC + 4 * c4]);
#pragma unroll
                    for (int r = 0; r < RPT; r++) {
                        acc[(4 * c4 + 0) * RPT + r] += v[r] * w.x;
                        acc[(4 * c4 + 1) * RPT + r] += v[r] * w.y;
                        acc[(4 * c4 + 2) * RPT + r] += v[r] * w.z;
                        acc[(4 * c4 + 3) * RPT + r] += v[r] * w.w;
                    }
                }
            } else {
#pragma unroll
                for (int co = 0; co < COC; co++) {
                    float w = s_w[k * COC + co];
#pragma unroll
                    for (int r = 0; r < RPT; r++)
                        acc[co * RPT + r] += v[r] * w;
                }
            }
        }
    }

    const int x = x0 + tx;
#pragma unroll
    for (int co = 0; co < COC; co++) {
        float bb = bias[co0 + co];
        size_t cbase = ((size_t)b * Ctot + co0 + co) * HW;
#pragma unroll
        for (int r = 0; r < RPT; r++) {
            float s = acc[co * RPT + r] + bb;
            if (ACT == ACT_RELU)      s = fmaxf(s, 0.f);
            else if (ACT == ACT_TANH) s = tanhf(s);
            else if (ACT == ACT_SIG)  s = 1.f / (1.f + expf(-s));
            out[cbase + (size_t)(y0 + ty + 8 * r) * W + x] = s;
        }
    }
}

// ===================================================================
// 2x2 maxpool, float4 vectorized.
// ===================================================================
__global__ void maxpool_kernel(const float* __restrict__ in,
                               float* __restrict__ out, int n4, int Ho, int Wo)
{
    int idx = blockIdx.x * 256 + threadIdx.x;
    if (idx >= n4) return;
    int Wo4 = Wo >> 2;
    int x4 = idx % Wo4;
    int t  = idx / Wo4;
    int y  = t % Ho;
    int bc = t / Ho;
    int Wi = Wo * 2;
    const float4* p0 = reinterpret_cast<const float4*>(
        in + ((size_t)bc * (Ho * 2) + 2 * y) * Wi + 8 * x4);
    const float4* p1 = reinterpret_cast<const float4*>(
        in + ((size_t)bc * (Ho * 2) + 2 * y + 1) * Wi + 8 * x4);
    float4 a0 = p0[0], a1 = p0[1];
    float4 b0 = p1[0], b1 = p1[1];
    float4 r;
    r.x = fmaxf(fmaxf(a0.x, a0.y), fmaxf(b0.x, b0.y));
    r.y = fmaxf(fmaxf(a0.z, a0.w), fmaxf(b0.z, b0.w));
    r.z = fmaxf(fmaxf(a1.x, a1.y), fmaxf(b1.x, b1.y));
    r.w = fmaxf(fmaxf(a1.z, a1.w), fmaxf(b1.z, b1.w));
    reinterpret_cast<float4*>(out)[idx] = r;
}

// ===================================================================
// LRNN horizontal: smem-transposed 32x32 chunks, fully coalesced.
// ===================================================================
__global__ void __launch_bounds__(256) lrnn_h_kernel(
    const float* __restrict__ xin, const float* __restrict__ fm,
    float* __restrict__ out)
{
    __shared__ float tX[32][33], tXr[32][33];
    __shared__ float tP0[32][33], tP0r[32][33];
    __shared__ float tP2[32][33], tP2r[32][33];
    __shared__ float tO[32][33];

    const int bc = blockIdx.y;
    const int c = bc & 15, b = bc >> 4;
    const int y0 = blockIdx.x * 32;
    const float* X  = xin + (((size_t)b * 16 + c) << 16);
    const float* P0 = fm  + (((size_t)b * 64 + c)      << 16);
    const float* P2 = fm  + (((size_t)b * 64 + 32 + c) << 16);
    float* O        = out + (((size_t)b * 16 + c) << 16);

    const int tid  = threadIdx.x;
    const int lrow = tid >> 5;
    const int lcol = tid & 31;

    float h0 = 0.f, h1 = 0.f, h2 = 0.f, h3 = 0.f;
    for (int ck = 0; ck < 8; ck++) {
        int k0 = ck * 32;
        int j0 = 224 - k0;
        __syncthreads();
#pragma unroll
        for (int rr = 0; rr < 32; rr += 8) {
            int row = rr + lrow;
            int gb = (y0 + row) << 8;
            tX [row][lcol] = X [gb + k0 + lcol];
            tXr[row][lcol] = X [gb + j0 + lcol];
            tP0[row][lcol] = P0[gb + k0 + lcol];
            tP0r[row][lcol]= P0[gb + j0 + lcol];
            tP2[row][lcol] = P2[gb + k0 + lcol];
            tP2r[row][lcol]= P2[gb + j0 + lcol];
        }
        __syncthreads();
        if (tid < 32) {
            const int t = tid;
#pragma unroll
            for (int kk = 0; kk < 32; kk++) {
                float xf = tX[t][kk],        xb = tXr[t][31 - kk];
                float p0 = tP0[t][kk],       p1 = tP2[t][kk];
                float p2 = tP0r[t][31 - kk], p3 = tP2r[t][31 - kk];
                h0 = xf + p0 * (h0 - xf);
                h1 = xf + p1 * (h1 - xf);
                h2 = xb + p2 * (h2 - xb);
                h3 = xb + p3 * (h3 - xb);
                tO[t][kk] = fmaxf(fmaxf(h0, h1), fmaxf(h2, h3));
            }
        }
        __syncthreads();
#pragma unroll
        for (int rr = 0; rr < 32; rr += 8) {
            int row = rr + lrow;
            O[((y0 + row) << 8) + k0 + lcol] = tO[row][lcol];
        }
    }
}

__global__ void lrnn_v_kernel(const float* __restrict__ xin,
                              const float* __restrict__ fm,
                              float* __restrict__ out)
{
    int r = blockIdx.x * 256 + threadIdx.x;
    if (r >= 8 * 16 * 256) return;
    int x = r & 255, c = (r >> 8) & 15, b = r >> 12;
    const float* X  = xin + (((size_t)b * 16 + c) << 16) + x;
    const float* P1 = fm  + (((size_t)b * 64 + 16 + c) << 16) + x;
    const float* P3 = fm  + (((size_t)b * 64 + 48 + c) << 16) + x;
    float* O        = out + (((size_t)b * 16 + c) << 16) + x;
    float h0 = 0.f, h1 = 0.f, h2 = 0.f, h3 = 0.f;
    for (int k = 0; k < 256; k++) {
        int ko = k << 8, jo = (255 - k) << 8;
        float xf = X[ko], xb = X[jo];
        float p0 = P1[ko], p1 = P3[ko], p2 = P1[jo], p3 = P3[jo];
        h0 = xf + p0 * (h0 - xf);
        h1 = xf + p1 * (h1 - xf);
        h2 = xb + p2 * (h2 - xb);
        h3 = xb + p3 * (h3 - xb);
        float m = fmaxf(fmaxf(h0, h1), fmaxf(h2, h3));
        O[ko] = fmaxf(O[ko], m);
    }
}

extern "C" void kernel_launch(void* const* d_in, const int* in_sizes, int n_in,
                              void* d_out, int out_size)
{
    const float* img = (const float*)d_in[0];
    const float* w1 = (const float*)d_in[1],  *b1 = (const float*)d_in[2];
    const float* w2 = (const float*)d_in[3],  *b2 = (const float*)d_in[4];
    const float* w3 = (const float*)d_in[5],  *b3 = (const float*)d_in[6];
    const float* w4 = (const float*)d_in[7],  *b4 = (const float*)d_in[8];
    const float* w5 = (const float*)d_in[9],  *b5 = (const float*)d_in[10];
    const float* w6 = (const float*)d_in[11], *b6 = (const float*)d_in[12];
    const float* w7 = (const float*)d_in[13], *b7 = (const float*)d_in[14];
    const float* w8 = (const float*)d_in[15], *b8 = (const float*)d_in[16];
    const float* w9 = (const float*)d_in[17], *b9 = (const float*)d_in[18];
    const float* wi = (const float*)d_in[19], *bi = (const float*)d_in[20];
    const float* wo = (const float*)d_in[21], *bo = (const float*)d_in[22];
    float* outp = (float*)d_out;

    float* buf = nullptr;
    cudaGetSymbolAddress((void**)&buf, g_buf);
    float* X1 = buf + O_X1;  float* P1 = buf + O_P1;
    float* X2 = buf + O_X2;  float* P2 = buf + O_P2;
    float* X3 = buf + O_X3;  float* P3 = buf + O_P3;
    float* X4 = buf + O_X4;  float* P4 = buf + O_P4;
    float* X5 = buf + O_X5;  float* X6 = buf + O_X6;
    float* X7 = buf + O_X7;  float* X8 = buf + O_X8;
    float* FM = buf + O_FM;  float* XIN = buf + O_XIN;
    float* RMAX = buf + O_RMAX;
    uint16_t* wph = (uint16_t*)(buf + O_WP);
    uint16_t* wpl = wph + WPLANE;

    auto tg = [](int W, int H) { return dim3(W / 16, H / 8, 8); };
    auto cgrid = [](int W, int H, int RPT, int nChunk) {
        return dim3(W / 16, H / (8 * RPT), 8 * nChunk);
    };
    auto pg4 = [](size_t n) { return dim3((unsigned)((n / 4 + 255) / 256)); };

    // ---- fused weight prep (1 launch) ----
    prep_all_kernel<<<(87040 + 255) / 256, 256>>>(w1, w2, w3, w7, w8, w9, wi, wph, wpl);

    // encoder
    tconv_kernel<5,16,ACT_RELU,0><<<tg(256,256),128>>>(img,15, nullptr,0, wph+WOFF1,wpl+WOFF1, b1, X1, 256,256, 0,16);
    maxpool_kernel<<<pg4(N_P1),256>>>(X1, P1, (int)(N_P1/4), 128,128);
    tconv_kernel<3,32,ACT_RELU,0><<<tg(128,128),128>>>(P1,16, nullptr,0, wph+WOFF2,wpl+WOFF2, b2, X2, 128,128, 0,32);
    maxpool_kernel<<<pg4(N_P2),256>>>(X2, P2, (int)(N_P2/4), 64,64);
    tconv_kernel<3,32,ACT_RELU,0><<<tg(64,64),128>>>(P2,32, nullptr,0, wph+WOFF3,wpl+WOFF3, b3, X3, 64,64, 0,32);
    maxpool_kernel<<<pg4(N_P3),256>>>(X3, P3, (int)(N_P3/4), 32,32);
    conv_kernel<3,16,ACT_RELU,1,0><<<cgrid(32,32,1,2),128>>>(P3,32, nullptr,0, w4,b4, X4, 32,32, 2,32);
    maxpool_kernel<<<pg4(N_P4),256>>>(X4, P4, (int)(N_P4/4), 16,16);
    conv_kernel<3,16,ACT_RELU,1,0><<<cgrid(16,16,1,4),128>>>(P4,32, nullptr,0, w5,b5, X5, 16,16, 4,64);

    // decoder (upsample fused into consumers)
    conv_kernel<3,16,ACT_RELU,1,1><<<cgrid(32,32,1,2),128>>>(X5,64, X4,32, w6,b6, X6, 32,32, 2,32);
    tconv_kernel<3,32,ACT_RELU,1><<<tg(64,64),128>>>(X6,32, X3,32, wph+WOFF7,wpl+WOFF7, b7, X7, 64,64, 0,32);
    tconv_kernel<3,32,ACT_RELU,1><<<tg(128,128),128>>>(X7,32, X2,32, wph+WOFF8,wpl+WOFF8, b8, X8, 128,128, 0,32);
    tconv_kernel<3,32,ACT_TANH,1><<<tg(256,256),128>>>(X8,32, X1,16, wph+WOFF9,wpl+WOFF9, b9, FM, 256,256, 0,64);
    tconv_kernel<3,32,ACT_TANH,1><<<tg(256,256),128>>>(X8,32, X1,16, wph+WOFF9,wpl+WOFF9, b9, FM, 256,256, 32,64);

    // input projection
    tconv_kernel<3,16,ACT_NONE,0><<<tg(256,256),128>>>(img,15, nullptr,0, wph+WOFFI,wpl+WOFFI, bi, XIN, 256,256, 0,16);

    // spatial RNN
    lrnn_h_kernel<<<dim3(8,128),256>>>(XIN, FM, RMAX);
    lrnn_v_kernel<<<128,256>>>(XIN, FM, RMAX);

    // output conv + sigmoid (scalar)
    conv_kernel<3,3,ACT_SIG,4,0><<<cgrid(256,256,4,1),128>>>(RMAX,16, nullptr,0, wo,bo, outp, 256,256, 1,3);
}

// round 17
// speedup vs baseline: 1.3266x; 1.3266x over previous
#include <cuda_runtime.h>
#include <cuda_bf16.h>
#include <math.h>
#include <stdint.h>

#define ACT_NONE 0
#define ACT_RELU 1
#define ACT_TANH 2
#define ACT_SIG  3

// ---- scratch buffer partition (floats) ----
constexpr size_t N_X1   = 8ull*16*256*256;
constexpr size_t N_P1   = 8ull*16*128*128;
constexpr size_t N_X2   = 8ull*32*128*128;
constexpr size_t N_P2   = 8ull*32*64*64;
constexpr size_t N_X3   = 8ull*32*64*64;
constexpr size_t N_P3   = 8ull*32*32*32;
constexpr size_t N_X4   = 8ull*32*32*32;
constexpr size_t N_P4   = 8ull*32*16*16;
constexpr size_t N_X5   = 8ull*64*16*16;
constexpr size_t N_X6   = 8ull*32*32*32;
constexpr size_t N_X7   = 8ull*32*64*64;
constexpr size_t N_X8   = 8ull*32*128*128;
constexpr size_t N_FM   = 8ull*64*256*256;
constexpr size_t N_XIN  = 8ull*16*256*256;
constexpr size_t N_RMAX = 8ull*16*256*256;
constexpr size_t N_WP   = 262144;

constexpr size_t O_X1   = 0;
constexpr size_t O_P1   = O_X1   + N_X1;
constexpr size_t O_X2   = O_P1   + N_P1;
constexpr size_t O_P2   = O_X2   + N_X2;
constexpr size_t O_X3   = O_P2   + N_P2;
constexpr size_t O_P3   = O_X3   + N_X3;
constexpr size_t O_X4   = O_P3   + N_P3;
constexpr size_t O_P4   = O_X4   + N_X4;
constexpr size_t O_X5   = O_P4   + N_P4;
constexpr size_t O_X6   = O_X5   + N_X5;
constexpr size_t O_X7   = O_X6   + N_X6;
constexpr size_t O_X8   = O_X7   + N_X7;
constexpr size_t O_FM   = O_X8   + N_X8;
constexpr size_t O_XIN  = O_FM   + N_FM;
constexpr size_t O_RMAX = O_XIN  + N_XIN;
constexpr size_t O_WP   = O_RMAX + N_RMAX;
constexpr size_t N_TOTAL = O_WP + N_WP;

__device__ float g_buf[N_TOTAL];

// prepped-weight offsets (u16 units; non-overlapping, verified)
constexpr int WOFF1 = 0;
constexpr int WOFF2 = 8192;
constexpr int WOFF3 = 16384;
constexpr int WOFF7 = 32768;
constexpr int WOFF8 = 53248;
constexpr int WOFF9 = 73728;
constexpr int WOFFI = 104448;
constexpr int WPLANE = 131072;

// ---- bf16 helpers ----
__device__ __forceinline__ void bf16_split(float v, uint16_t& hi, uint16_t& lo) {
    __nv_bfloat16 h = __float2bfloat16_rn(v);
    hi = __bfloat16_as_ushort(h);
    lo = __bfloat16_as_ushort(__float2bfloat16_rn(v - __bfloat162float(h)));
}
__device__ __forceinline__ int idx16(int c) {
    return (c < 8) ? (((c >> 1) << 2) + (c & 1))
                   : ((((c - 8) >> 1) << 2) + 2 + ((c - 8) & 1));
}
__device__ __forceinline__ void mma_bf16(float* c, const uint32_t* a,
                                         uint32_t b0, uint32_t b1) {
    asm volatile(
        "mma.sync.aligned.m16n8k16.row.col.f32.bf16.bf16.f32 "
        "{%0,%1,%2,%3}, {%4,%5,%6,%7}, {%8,%9}, {%0,%1,%2,%3};"
        : "+f"(c[0]), "+f"(c[1]), "+f"(c[2]), "+f"(c[3])
        : "r"(a[0]), "r"(a[1]), "r"(a[2]), "r"(a[3]), "r"(b0), "r"(b1));
}
// bilinear 2x upsample sample, half-pixel centers, edge clamp.
__device__ __forceinline__ float ups_sample(const float* __restrict__ p,
                                            int y, int x, int Hi, int Wi) {
    int xi = x >> 1, yi = y >> 1;
    int xa, xb; float wxa;
    if (x & 1) { xa = xi; xb = min(xi + 1, Wi - 1); wxa = 0.75f; }
    else       { xa = max(xi - 1, 0); xb = xi;      wxa = 0.25f; }
    int ya, yb; float wya;
    if (y & 1) { ya = yi; yb = min(yi + 1, Hi - 1); wya = 0.75f; }
    else       { ya = max(yi - 1, 0); yb = yi;      wya = 0.25f; }
    float r0 = wxa * p[ya * Wi + xa] + (1.f - wxa) * p[ya * Wi + xb];
    float r1 = wxa * p[yb * Wi + xa] + (1.f - wxa) * p[yb * Wi + xb];
    return wya * r0 + (1.f - wya) * r1;
}

// ===================================================================
// Fused weight prep (verified).
// ===================================================================
__global__ void prep_all_kernel(
    const float* __restrict__ w1, const float* __restrict__ w2,
    const float* __restrict__ w3, const float* __restrict__ w7,
    const float* __restrict__ w8, const float* __restrict__ w9,
    const float* __restrict__ wi,
    uint16_t* __restrict__ wph, uint16_t* __restrict__ wpl)
{
    const int cum[8] = {0, 6400, 11008, 20224, 38656, 57088, 84736, 87040};
    int idx = blockIdx.x * 256 + threadIdx.x;
    if (idx >= 87040) return;
    int l = 0;
    while (idx >= cum[l + 1]) l++;
    int local = idx - cum[l];

    const float* wsrc; int Cin, Cout, KK, woff;
    switch (l) {
        case 0: wsrc = w1; Cin = 15; Cout = 16; KK = 25; woff = WOFF1; break;
        case 1: wsrc = w2; Cin = 16; Cout = 32; KK = 9;  woff = WOFF2; break;
        case 2: wsrc = w3; Cin = 32; Cout = 32; KK = 9;  woff = WOFF3; break;
        case 3: wsrc = w7; Cin = 64; Cout = 32; KK = 9;  woff = WOFF7; break;
        case 4: wsrc = w8; Cin = 64; Cout = 32; KK = 9;  woff = WOFF8; break;
        case 5: wsrc = w9; Cin = 48; Cout = 64; KK = 9;  woff = WOFF9; break;
        default: wsrc = wi; Cin = 15; Cout = 16; KK = 9; woff = WOFFI; break;
    }
    int ch = local & 15;
    int r  = local >> 4;
    int n  = r % Cout;
    int r2 = r / Cout;
    int t  = r2 % KK;
    int g  = r2 / KK;
    int cin = g * 16 + ch;
    float w = (cin < Cin) ? wsrc[((size_t)n * Cin + cin) * KK + t] : 0.f;
    uint16_t h, lo;
    bf16_split(w, h, lo);
    int p = woff + ((g * KK + t) * Cout + n) * 16 + idx16(ch);
    wph[p] = h;
    wpl[p] = lo;
}

// ===================================================================
// Tensor conv (R15-proven; staging with bounded unroll hint).
// ===================================================================
template<int K, int N, int ACT, int UPSA>
__global__ void __launch_bounds__(128) tconv_kernel(
    const float* __restrict__ inA, int CA,
    const float* __restrict__ inB, int CB,
    const uint16_t* __restrict__ wph, const uint16_t* __restrict__ wpl,
    const float* __restrict__ bias,
    float* __restrict__ out, int H, int W, int co0, int Ctot)
{
    constexpr int KK   = K * K;
    constexpr int PAD  = K / 2;
    constexpr int SH   = 8 + K - 1;
    constexpr int SWI  = 16 + K - 1;
    constexpr int NPIX = SH * SWI;
    constexpr int RP   = 16;
    constexpr int NT   = N / 8;
    constexpr int TOT  = 16 * NPIX;
    constexpr int SITER = (TOT + 127) / 128;

    __shared__ __align__(16) uint16_t s_hi[NPIX * RP];
    __shared__ __align__(16) uint16_t s_lo[NPIX * RP];
    __shared__ __align__(16) uint16_t s_bh[KK * N * RP];
    __shared__ __align__(16) uint16_t s_bl[KK * N * RP];

    const int tid  = threadIdx.x;
    const int wid  = tid >> 5;
    const int lane = tid & 31;
    const int ql   = lane & 3;
    const int qr   = lane >> 2;
    const int x0 = blockIdx.x * 16, y0 = blockIdx.y * 8, b = blockIdx.z;
    const int Cin = CA + CB;
    const size_t HW  = (size_t)H * W;
    const size_t HWA = UPSA ? (HW >> 2) : HW;
    const int Hi = H >> 1, Wi = W >> 1;

    float acc[2][NT][4];
#pragma unroll
    for (int mt = 0; mt < 2; mt++)
#pragma unroll
        for (int nt = 0; nt < NT; nt++)
#pragma unroll
            for (int i = 0; i < 4; i++) acc[mt][nt][i] = 0.f;

    const int nG = (Cin + 15) >> 4;
    for (int gi = 0; gi < nG; gi++) {
        const int g0 = gi * 16;
        __syncthreads();
        // ---- stage halo (bounded unroll -> compiler-scheduled MLP) ----
#pragma unroll 4
        for (int s = 0; s < SITER; s++) {
            int idx = tid + s * 128;
            if (idx < TOT) {
                int ch  = idx / NPIX;
                int pix = idx - ch * NPIX;
                int iy = pix / SWI, ix = pix - iy * SWI;
                int cin = g0 + ch;
                float v = 0.f;
                if (cin < Cin) {
                    int gy = y0 + iy - PAD, gx = x0 + ix - PAD;
                    if ((unsigned)gy < (unsigned)H && (unsigned)gx < (unsigned)W) {
                        if (cin < CA) {
                            const float* src = inA + ((size_t)b * CA + cin) * HWA;
                            v = UPSA ? ups_sample(src, gy, gx, Hi, Wi)
                                     : src[(size_t)gy * W + gx];
                        } else {
                            const float* src = inB + ((size_t)b * CB + (cin - CA)) * HW;
                            v = src[(size_t)gy * W + gx];
                        }
                    }
                }
                uint16_t h, l;
                bf16_split(v, h, l);
                int p = pix * RP + idx16(ch);
                s_hi[p] = h;
                s_lo[p] = l;
            }
        }
        // ---- copy B records gmem -> smem, uint4 (contiguous) ----
        {
            const uint4* srcH = reinterpret_cast<const uint4*>(wph);
            const uint4* srcL = reinterpret_cast<const uint4*>(wpl);
            uint4* dstH = reinterpret_cast<uint4*>(s_bh);
            uint4* dstL = reinterpret_cast<uint4*>(s_bl);
#pragma unroll 4
            for (int u = tid; u < KK * N * 2; u += 128) {
                int q = u & 1;
                int r = u >> 1;
                int n = r % N;
                int t = r / N;
                int su = ((gi * KK + t) * Ctot + co0 + n) * 2 + q;
                dstH[u] = srcH[su];
                dstL[u] = srcL[su];
            }
        }
        __syncthreads();

        // ---- compute: KK taps ----
#pragma unroll
        for (int ky = 0; ky < K; ky++)
#pragma unroll
        for (int kx = 0; kx < K; kx++) {
            const int t = ky * K + kx;
            uint32_t aH[2][4], aL[2][4];
#pragma unroll
            for (int mt = 0; mt < 2; mt++) {
                int pixA = (2 * wid + mt + ky) * SWI + (qr + kx);
                uint2 h0 = *reinterpret_cast<const uint2*>(
                    &s_hi[pixA * RP + 4 * ql]);
                uint2 h1 = *reinterpret_cast<const uint2*>(
                    &s_hi[(pixA + 8) * RP + 4 * ql]);
                uint2 l0 = *reinterpret_cast<const uint2*>(
                    &s_lo[pixA * RP + 4 * ql]);
                uint2 l1 = *reinterpret_cast<const uint2*>(
                    &s_lo[(pixA + 8) * RP + 4 * ql]);
                aH[mt][0] = h0.x; aH[mt][1] = h1.x;
                aH[mt][2] = h0.y; aH[mt][3] = h1.y;
                aL[mt][0] = l0.x; aL[mt][1] = l1.x;
                aL[mt][2] = l0.y; aL[mt][3] = l1.y;
            }
#pragma unroll
            for (int nt = 0; nt < NT; nt++) {
                uint2 bh = *reinterpret_cast<const uint2*>(
                    &s_bh[(t * N + nt * 8 + qr) * RP + 4 * ql]);
                uint2 bl = *reinterpret_cast<const uint2*>(
                    &s_bl[(t * N + nt * 8 + qr) * RP + 4 * ql]);
#pragma unroll
                for (int mt = 0; mt < 2; mt++) {
                    mma_bf16(acc[mt][nt], aH[mt], bh.x, bh.y);
                    mma_bf16(acc[mt][nt], aH[mt], bl.x, bl.y);
                    mma_bf16(acc[mt][nt], aL[mt], bh.x, bh.y);
                }
            }
        }
    }

    // ---- epilogue ----
#pragma unroll
    for (int mt = 0; mt < 2; mt++) {
        int gy = y0 + 2 * wid + mt;
#pragma unroll
        for (int nt = 0; nt < NT; nt++) {
#pragma unroll
            for (int i = 0; i < 4; i++) {
                int co = co0 + nt * 8 + 2 * ql + (i & 1);
                int gx = x0 + qr + ((i >> 1) ? 8 : 0);
                float s = acc[mt][nt][i] + bias[co];
                if (ACT == ACT_RELU)      s = fmaxf(s, 0.f);
                else if (ACT == ACT_TANH) s = tanhf(s);
                else if (ACT == ACT_SIG)  s = 1.f / (1.f + expf(-s));
                out[((size_t)b * Ctot + co) * HW + (size_t)gy * W + gx] = s;
            }
        }
    }
}

// ===================================================================
// Scalar conv (R3 proven), optional fused upsample on inA.
// ===================================================================
template<int K, int COC, int ACT, int RPT, int UPSA>
__global__ void __launch_bounds__(128) conv_kernel(
    const float* __restrict__ inA, int CA,
    const float* __restrict__ inB, int CB,
    const float* __restrict__ wgt, const float* __restrict__ bias,
    float* __restrict__ out, int H, int W, int nChunk, int Ctot)
{
    constexpr int KK = K * K, PAD = K / 2, TH = 8 * RPT;
    constexpr int SW = (K == 3) ? 18 : 22;
    constexpr int SH = TH + K - 1;
    __shared__ float s_in[SH * SW];
    __shared__ __align__(16) float s_w[KK * COC];

    const int tx = threadIdx.x & 15, ty = threadIdx.x >> 4;
    const int x0 = blockIdx.x * 16, y0 = blockIdx.y * TH;
    const int z = blockIdx.z;
    const int b = z / nChunk, chunk = z - b * nChunk, co0 = chunk * COC;
    const int Cin = CA + CB;
    const size_t HW = (size_t)H * W;
    const size_t HWA = UPSA ? (HW >> 2) : HW;
    const int Hi = H >> 1, Wi = W >> 1;

    float acc[COC * RPT];
#pragma unroll
    for (int i = 0; i < COC * RPT; i++) acc[i] = 0.f;

    for (int cin = 0; cin < Cin; cin++) {
        __syncthreads();
#pragma unroll 2
        for (int i = threadIdx.x; i < SH * SW; i += 128) {
            int iy = i / SW, ix = i - iy * SW;
            int gy = y0 + iy - PAD, gx = x0 + ix - PAD;
            float v = 0.f;
            if ((unsigned)gy < (unsigned)H && (unsigned)gx < (unsigned)W) {
                if (cin < CA) {
                    const float* src = inA + ((size_t)b * CA + cin) * HWA;
                    v = UPSA ? ups_sample(src, gy, gx, Hi, Wi)
                             : src[(size_t)gy * W + gx];
                } else {
                    const float* src = inB + ((size_t)b * CB + (cin - CA)) * HW;
                    v = src[(size_t)gy * W + gx];
                }
            }
            s_in[i] = v;
        }
        for (int i = threadIdx.x; i < KK * COC; i += 128) {
            int k = i / COC, co = i - k * COC;
            s_w[i] = wgt[((size_t)(co0 + co) * Cin + cin) * KK + k];
        }
        __syncthreads();

#pragma unroll
        for (int k = 0; k < KK; k++) {
            const int ky = k / K, kx = k - ky * K;
            float v[RPT];
#pragma unroll
            for (int r = 0; r < RPT; r++)
                v[r] = s_in[(ty + 8 * r + ky) * SW + tx + kx];
            if (COC % 4 == 0) {
#pragma unroll
                for (int c4 = 0; c4 < COC / 4; c4++) {
                    float4 w = *reinterpret_cast<const float4*>(&s_w[k * COC + 4 * c4]);
#pragma unroll
                    for (int r = 0; r < RPT; r++) {
                        acc[(4 * c4 + 0) * RPT + r] += v[r] * w.x;
                        acc[(4 * c4 + 1) * RPT + r] += v[r] * w.y;
                        acc[(4 * c4 + 2) * RPT + r] += v[r] * w.z;
                        acc[(4 * c4 + 3) * RPT + r] += v[r] * w.w;
                    }
                }
            } else {
#pragma unroll
                for (int co = 0; co < COC; co++) {
                    float w = s_w[k * COC + co];
#pragma unroll
                    for (int r = 0; r < RPT; r++)
                        acc[co * RPT + r] += v[r] * w;
                }
            }
        }
    }

    const int x = x0 + tx;
#pragma unroll
    for (int co = 0; co < COC; co++) {
        float bb = bias[co0 + co];
        size_t cbase = ((size_t)b * Ctot + co0 + co) * HW;
#pragma unroll
        for (int r = 0; r < RPT; r++) {
            float s = acc[co * RPT + r] + bb;
            if (ACT == ACT_RELU)      s = fmaxf(s, 0.f);
            else if (ACT == ACT_TANH) s = tanhf(s);
            else if (ACT == ACT_SIG)  s = 1.f / (1.f + expf(-s));
            out[cbase + (size_t)(y0 + ty + 8 * r) * W + x] = s;
        }
    }
}

// ===================================================================
// 2x2 maxpool, float4 vectorized.
// ===================================================================
__global__ void maxpool_kernel(const float* __restrict__ in,
                               float* __restrict__ out, int n4, int Ho, int Wo)
{
    int idx = blockIdx.x * 256 + threadIdx.x;
    if (idx >= n4) return;
    int Wo4 = Wo >> 2;
    int x4 = idx % Wo4;
    int t  = idx / Wo4;
    int y  = t % Ho;
    int bc = t / Ho;
    int Wi = Wo * 2;
    const float4* p0 = reinterpret_cast<const float4*>(
        in + ((size_t)bc * (Ho * 2) + 2 * y) * Wi + 8 * x4);
    const float4* p1 = reinterpret_cast<const float4*>(
        in + ((size_t)bc * (Ho * 2) + 2 * y + 1) * Wi + 8 * x4);
    float4 a0 = p0[0], a1 = p0[1];
    float4 b0 = p1[0], b1 = p1[1];
    float4 r;
    r.x = fmaxf(fmaxf(a0.x, a0.y), fmaxf(b0.x, b0.y));
    r.y = fmaxf(fmaxf(a0.z, a0.w), fmaxf(b0.z, b0.w));
    r.z = fmaxf(fmaxf(a1.x, a1.y), fmaxf(b1.x, b1.y));
    r.w = fmaxf(fmaxf(a1.z, a1.w), fmaxf(b1.z, b1.w));
    reinterpret_cast<float4*>(out)[idx] = r;
}

// ===================================================================
// LRNN horizontal: smem-transposed 32x32 chunks, fully coalesced.
// ===================================================================
__global__ void __launch_bounds__(256) lrnn_h_kernel(
    const float* __restrict__ xin, const float* __restrict__ fm,
    float* __restrict__ out)
{
    __shared__ float tX[32][33], tXr[32][33];
    __shared__ float tP0[32][33], tP0r[32][33];
    __shared__ float tP2[32][33], tP2r[32][33];
    __shared__ float tO[32][33];

    const int bc = blockIdx.y;
    const int c = bc & 15, b = bc >> 4;
    const int y0 = blockIdx.x * 32;
    const float* X  = xin + (((size_t)b * 16 + c) << 16);
    const float* P0 = fm  + (((size_t)b * 64 + c)      << 16);
    const float* P2 = fm  + (((size_t)b * 64 + 32 + c) << 16);
    float* O        = out + (((size_t)b * 16 + c) << 16);

    const int tid  = threadIdx.x;
    const int lrow = tid >> 5;
    const int lcol = tid & 31;

    float h0 = 0.f, h1 = 0.f, h2 = 0.f, h3 = 0.f;
    for (int ck = 0; ck < 8; ck++) {
        int k0 = ck * 32;
        int j0 = 224 - k0;
        __syncthreads();
#pragma unroll
        for (int rr = 0; rr < 32; rr += 8) {
            int row = rr + lrow;
            int gb = (y0 + row) << 8;
            tX [row][lcol] = X [gb + k0 + lcol];
            tXr[row][lcol] = X [gb + j0 + lcol];
            tP0[row][lcol] = P0[gb + k0 + lcol];
            tP0r[row][lcol]= P0[gb + j0 + lcol];
            tP2[row][lcol] = P2[gb + k0 + lcol];
            tP2r[row][lcol]= P2[gb + j0 + lcol];
        }
        __syncthreads();
        if (tid < 32) {
            const int t = tid;
#pragma unroll
            for (int kk = 0; kk < 32; kk++) {
                float xf = tX[t][kk],        xb = tXr[t][31 - kk];
                float p0 = tP0[t][kk],       p1 = tP2[t][kk];
                float p2 = tP0r[t][31 - kk], p3 = tP2r[t][31 - kk];
                h0 = xf + p0 * (h0 - xf);
                h1 = xf + p1 * (h1 - xf);
                h2 = xb + p2 * (h2 - xb);
                h3 = xb + p3 * (h3 - xb);
                tO[t][kk] = fmaxf(fmaxf(h0, h1), fmaxf(h2, h3));
            }
        }
        __syncthreads();
#pragma unroll
        for (int rr = 0; rr < 32; rr += 8) {
            int row = rr + lrow;
            O[((y0 + row) << 8) + k0 + lcol] = tO[row][lcol];
        }
    }
}

__global__ void lrnn_v_kernel(const float* __restrict__ xin,
                              const float* __restrict__ fm,
                              float* __restrict__ out)
{
    int r = blockIdx.x * 256 + threadIdx.x;
    if (r >= 8 * 16 * 256) return;
    int x = r & 255, c = (r >> 8) & 15, b = r >> 12;
    const float* X  = xin + (((size_t)b * 16 + c) << 16) + x;
    const float* P1 = fm  + (((size_t)b * 64 + 16 + c) << 16) + x;
    const float* P3 = fm  + (((size_t)b * 64 + 48 + c) << 16) + x;
    float* O        = out + (((size_t)b * 16 + c) << 16) + x;
    float h0 = 0.f, h1 = 0.f, h2 = 0.f, h3 = 0.f;
    for (int k = 0; k < 256; k++) {
        int ko = k << 8, jo = (255 - k) << 8;
        float xf = X[ko], xb = X[jo];
        float p0 = P1[ko], p1 = P3[ko], p2 = P1[jo], p3 = P3[jo];
        h0 = xf + p0 * (h0 - xf);
        h1 = xf + p1 * (h1 - xf);
        h2 = xb + p2 * (h2 - xb);
        h3 = xb + p3 * (h3 - xb);
        float m = fmaxf(fmaxf(h0, h1), fmaxf(h2, h3));
        O[ko] = fmaxf(O[ko], m);
    }
}

extern "C" void kernel_launch(void* const* d_in, const int* in_sizes, int n_in,
                              void* d_out, int out_size)
{
    const float* img = (const float*)d_in[0];
    const float* w1 = (const float*)d_in[1],  *b1 = (const float*)d_in[2];
    const float* w2 = (const float*)d_in[3],  *b2 = (const float*)d_in[4];
    const float* w3 = (const float*)d_in[5],  *b3 = (const float*)d_in[6];
    const float* w4 = (const float*)d_in[7],  *b4 = (const float*)d_in[8];
    const float* w5 = (const float*)d_in[9],  *b5 = (const float*)d_in[10];
    const float* w6 = (const float*)d_in[11], *b6 = (const float*)d_in[12];
    const float* w7 = (const float*)d_in[13], *b7 = (const float*)d_in[14];
    const float* w8 = (const float*)d_in[15], *b8 = (const float*)d_in[16];
    const float* w9 = (const float*)d_in[17], *b9 = (const float*)d_in[18];
    const float* wi = (const float*)d_in[19], *bi = (const float*)d_in[20];
    const float* wo = (const float*)d_in[21], *bo = (const float*)d_in[22];
    float* outp = (float*)d_out;

    float* buf = nullptr;
    cudaGetSymbolAddress((void**)&buf, g_buf);
    float* X1 = buf + O_X1;  float* P1 = buf + O_P1;
    float* X2 = buf + O_X2;  float* P2 = buf + O_P2;
    float* X3 = buf + O_X3;  float* P3 = buf + O_P3;
    float* X4 = buf + O_X4;  float* P4 = buf + O_P4;
    float* X5 = buf + O_X5;  float* X6 = buf + O_X6;
    float* X7 = buf + O_X7;  float* X8 = buf + O_X8;
    float* FM = buf + O_FM;  float* XIN = buf + O_XIN;
    float* RMAX = buf + O_RMAX;
    uint16_t* wph = (uint16_t*)(buf + O_WP);
    uint16_t* wpl = wph + WPLANE;

    auto tg = [](int W, int H) { return dim3(W / 16, H / 8, 8); };
    auto cgrid = [](int W, int H, int RPT, int nChunk) {
        return dim3(W / 16, H / (8 * RPT), 8 * nChunk);
    };
    auto pg4 = [](size_t n) { return dim3((unsigned)((n / 4 + 255) / 256)); };

    // ---- fused weight prep (1 launch) ----
    prep_all_kernel<<<(87040 + 255) / 256, 256>>>(w1, w2, w3, w7, w8, w9, wi, wph, wpl);

    // encoder
    tconv_kernel<5,16,ACT_RELU,0><<<tg(256,256),128>>>(img,15, nullptr,0, wph+WOFF1,wpl+WOFF1, b1, X1, 256,256, 0,16);
    maxpool_kernel<<<pg4(N_P1),256>>>(X1, P1, (int)(N_P1/4), 128,128);
    tconv_kernel<3,32,ACT_RELU,0><<<tg(128,128),128>>>(P1,16, nullptr,0, wph+WOFF2,wpl+WOFF2, b2, X2, 128,128, 0,32);
    maxpool_kernel<<<pg4(N_P2),256>>>(X2, P2, (int)(N_P2/4), 64,64);
    tconv_kernel<3,32,ACT_RELU,0><<<tg(64,64),128>>>(P2,32, nullptr,0, wph+WOFF3,wpl+WOFF3, b3, X3, 64,64, 0,32);
    maxpool_kernel<<<pg4(N_P3),256>>>(X3, P3, (int)(N_P3/4), 32,32);
    conv_kernel<3,16,ACT_RELU,1,0><<<cgrid(32,32,1,2),128>>>(P3,32, nullptr,0, w4,b4, X4, 32,32, 2,32);
    maxpool_kernel<<<pg4(N_P4),256>>>(X4, P4, (int)(N_P4/4), 16,16);
    conv_kernel<3,16,ACT_RELU,1,0><<<cgrid(16,16,1,4),128>>>(P4,32, nullptr,0, w5,b5, X5, 16,16, 4,64);

    // decoder (upsample fused into consumers)
    conv_kernel<3,16,ACT_RELU,1,1><<<cgrid(32,32,1,2),128>>>(X5,64, X4,32, w6,b6, X6, 32,32, 2,32);
    tconv_kernel<3,32,ACT_RELU,1><<<tg(64,64),128>>>(X6,32, X3,32, wph+WOFF7,wpl+WOFF7, b7, X7, 64,64, 0,32);
    tconv_kernel<3,32,ACT_RELU,1><<<tg(128,128),128>>>(X7,32, X2,32, wph+WOFF8,wpl+WOFF8, b8, X8, 128,128, 0,32);
    tconv_kernel<3,32,ACT_TANH,1><<<tg(256,256),128>>>(X8,32, X1,16, wph+WOFF9,wpl+WOFF9, b9, FM, 256,256, 0,64);
    tconv_kernel<3,32,ACT_TANH,1><<<tg(256,256),128>>>(X8,32, X1,16, wph+WOFF9,wpl+WOFF9, b9, FM, 256,256, 32,64);

    // input projection
    tconv_kernel<3,16,ACT_NONE,0><<<tg(256,256),128>>>(img,15, nullptr,0, wph+WOFFI,wpl+WOFFI, bi, XIN, 256,256, 0,16);

    // spatial RNN
    lrnn_h_kernel<<<dim3(8,128),256>>>(XIN, FM, RMAX);
    lrnn_v_kernel<<<128,256>>>(XIN, FM, RMAX);

    // output conv + sigmoid (scalar)
    conv_kernel<3,3,ACT_SIG,4,0><<<cgrid(256,256,4,1),128>>>(RMAX,16, nullptr,0, wo,bo, outp, 256,256, 1,3);
}